// round 4
// baseline (speedup 1.0000x reference)
#include <cuda_runtime.h>

// out[b,i,n] = sum_j w[i,j] * x[b,j,n]
// x: [256, 3, 65536] fp32, w: [3,3] fp32, out: [256, 3, 65536] fp32
//
// HBM-bound streamer. v2: 2 float4 positions per thread (block-strided,
// coalesced), 6 front-batched evict-first loads, streaming stores.

static constexpr int N_COLS  = 65536;
static constexpr int N4      = N_COLS / 4;          // 16384 float4 per row
static constexpr int BATCH   = 256;
static constexpr long TOTAL4 = (long)BATCH * N4;    // 4,194,304 float4 triples
static constexpr int VPT     = 2;                   // float4 per thread
static constexpr int TPB     = 256;
static constexpr int PER_BLK = TPB * VPT;           // 512 (divides N4)

__global__ __launch_bounds__(TPB) void rot3_kernel_v2(
    const float4* __restrict__ x,
    const float*  __restrict__ w,
    float4* __restrict__ out)
{
    // Block covers 512 consecutive float4 positions; since 512 | 16384,
    // all positions in a block share the same batch index b.
    long base = (long)blockIdx.x * PER_BLK + threadIdx.x;
    int b  = (int)(base >> 14);          // base / N4
    int n0 = (int)(base & (N4 - 1));     // base % N4
    int n1 = n0 + TPB;                   // second position, same b

    float w00 = __ldg(w + 0), w01 = __ldg(w + 1), w02 = __ldg(w + 2);
    float w10 = __ldg(w + 3), w11 = __ldg(w + 4), w12 = __ldg(w + 5);
    float w20 = __ldg(w + 6), w21 = __ldg(w + 7), w22 = __ldg(w + 8);

    const float4* xb = x + (size_t)b * 3 * N4;

    // 6 independent evict-first loads, front-batched for max MLP.
    float4 a0 = __ldcs(xb + n0);
    float4 a1 = __ldcs(xb + N4 + n0);
    float4 a2 = __ldcs(xb + 2 * N4 + n0);
    float4 c0 = __ldcs(xb + n1);
    float4 c1 = __ldcs(xb + N4 + n1);
    float4 c2 = __ldcs(xb + 2 * N4 + n1);

    float4* ob = out + (size_t)b * 3 * N4;

    float4 o;
    // position n0
    o.x = w00*a0.x + w01*a1.x + w02*a2.x;
    o.y = w00*a0.y + w01*a1.y + w02*a2.y;
    o.z = w00*a0.z + w01*a1.z + w02*a2.z;
    o.w = w00*a0.w + w01*a1.w + w02*a2.w;
    __stcs(ob + n0, o);
    o.x = w10*a0.x + w11*a1.x + w12*a2.x;
    o.y = w10*a0.y + w11*a1.y + w12*a2.y;
    o.z = w10*a0.z + w11*a1.z + w12*a2.z;
    o.w = w10*a0.w + w11*a1.w + w12*a2.w;
    __stcs(ob + N4 + n0, o);
    o.x = w20*a0.x + w21*a1.x + w22*a2.x;
    o.y = w20*a0.y + w21*a1.y + w22*a2.y;
    o.z = w20*a0.z + w21*a1.z + w22*a2.z;
    o.w = w20*a0.w + w21*a1.w + w22*a2.w;
    __stcs(ob + 2 * N4 + n0, o);

    // position n1
    o.x = w00*c0.x + w01*c1.x + w02*c2.x;
    o.y = w00*c0.y + w01*c1.y + w02*c2.y;
    o.z = w00*c0.z + w01*c1.z + w02*c2.z;
    o.w = w00*c0.w + w01*c1.w + w02*c2.w;
    __stcs(ob + n1, o);
    o.x = w10*c0.x + w11*c1.x + w12*c2.x;
    o.y = w10*c0.y + w11*c1.y + w12*c2.y;
    o.z = w10*c0.z + w11*c1.z + w12*c2.z;
    o.w = w10*c0.w + w11*c1.w + w12*c2.w;
    __stcs(ob + N4 + n1, o);
    o.x = w20*c0.x + w21*c1.x + w22*c2.x;
    o.y = w20*c0.y + w21*c1.y + w22*c2.y;
    o.z = w20*c0.z + w21*c1.z + w22*c2.z;
    o.w = w20*c0.w + w21*c1.w + w22*c2.w;
    __stcs(ob + 2 * N4 + n1, o);
}

extern "C" void kernel_launch(void* const* d_in, const int* in_sizes, int n_in,
                              void* d_out, int out_size)
{
    const float4* x = (const float4*)d_in[0];
    const float*  w = (const float*)d_in[1];
    float4* out = (float4*)d_out;

    const long blocks = TOTAL4 / PER_BLK;  // 8192
    rot3_kernel_v2<<<(int)blocks, TPB>>>(x, w, out);
}